// round 1
// baseline (speedup 1.0000x reference)
#include <cuda_runtime.h>
#include <math.h>

// Problem constants
#define BN 64      // batch
#define TT 32      // timesteps
#define HD 1024    // hidden = embed dim
#define LL 196     // image feature locations
#define G4 4096    // 4*H

// ---------------- scratch (device globals; no allocations allowed) ----------
__device__ float g_X1[(size_t)2048 * 4096];   // precomputed x@w_ih1^T + b_ih1 + b_hh1, 32MB
__device__ float g_gates[BN * G4];            // per-step gate preactivations
__device__ float g_h1[BN * HD];
__device__ float g_c1[BN * HD];
__device__ float g_h2[BN * HD];
__device__ float g_c2[BN * HD];
__device__ float g_alpha[BN * LL];
__device__ float g_vatt[BN * HD];

// ---------------- init ------------------------------------------------------
__global__ void zero_state() {
    int i = blockIdx.x * blockDim.x + threadIdx.x;
    if (i < BN * HD) { g_h1[i] = 0.f; g_c1[i] = 0.f; g_h2[i] = 0.f; g_c2[i] = 0.f; }
}

// ---------------- precompute X1 = gather(emb, tok) @ w_ih1^T + b_ih1 + b_hh1 -
// C is (2048 x 4096), K = 1024. Tile 64x64, 256 threads, 4x4 micro.
__global__ __launch_bounds__(256) void gemm_x1(
    const int* __restrict__ inp, const float* __restrict__ emb,
    const float* __restrict__ w, const float* __restrict__ b1,
    const float* __restrict__ b2)
{
    __shared__ float As[16][68];
    __shared__ float Bs[16][68];
    __shared__ int tok[64];

    const int tid = threadIdx.x;
    const int r0 = blockIdx.y * 64;
    const int c0 = blockIdx.x * 64;

    if (tid < 64) tok[tid] = inp[r0 + tid];
    __syncthreads();

    const int lr = tid >> 2;            // 0..63
    const int lk = (tid & 3) * 4;       // 0,4,8,12
    const int ty = tid >> 4;            // 0..15
    const int tx = tid & 15;            // 0..15

    float acc[4][4] = {};

    for (int kt = 0; kt < 1024; kt += 16) {
        float4 a  = *(const float4*)(emb + (size_t)tok[lr] * 1024 + kt + lk);
        float4 bv = *(const float4*)(w   + (size_t)(c0 + lr) * 1024 + kt + lk);
        As[lk + 0][lr] = a.x;  As[lk + 1][lr] = a.y;
        As[lk + 2][lr] = a.z;  As[lk + 3][lr] = a.w;
        Bs[lk + 0][lr] = bv.x; Bs[lk + 1][lr] = bv.y;
        Bs[lk + 2][lr] = bv.z; Bs[lk + 3][lr] = bv.w;
        __syncthreads();

        #pragma unroll
        for (int k = 0; k < 16; k++) {
            float4 av = *(const float4*)&As[k][ty * 4];
            float4 bw = *(const float4*)&Bs[k][tx * 4];
            float ar[4] = {av.x, av.y, av.z, av.w};
            float br[4] = {bw.x, bw.y, bw.z, bw.w};
            #pragma unroll
            for (int i = 0; i < 4; i++)
                #pragma unroll
                for (int j = 0; j < 4; j++)
                    acc[i][j] += ar[i] * br[j];
        }
        __syncthreads();
    }

    #pragma unroll
    for (int i = 0; i < 4; i++)
        #pragma unroll
        for (int j = 0; j < 4; j++) {
            int r = r0 + ty * 4 + i;
            int c = c0 + tx * 4 + j;
            g_X1[(size_t)r * 4096 + c] = acc[i][j] + b1[c] + b2[c];
        }
}

// ---------------- per-step gates GEMM ---------------------------------------
// C (64 x 4096) = sum over up to 3 segments of A_s(64x1024) @ B_s(4096x1024)^T
//   mode 1: gates1 = g_X1[t] + h1 @ w_hh1^T
//   mode 2: gates2 = vatt @ w_ih2[:, :H]^T + h1 @ w_ih2[:, H:]^T + h2 @ w_hh2^T + b_ih2 + b_hh2
// Tile 64x32, 128 threads, 4x4 micro.
__global__ __launch_bounds__(128) void gemm_gates(
    int mode, int t,
    const float* __restrict__ w_hh1,
    const float* __restrict__ w_ih2,
    const float* __restrict__ w_hh2,
    const float* __restrict__ b_ih2,
    const float* __restrict__ b_hh2)
{
    __shared__ float As[16][68];
    __shared__ float Bs[16][36];

    const float* Aseg[3];
    const float* Bseg[3];
    int bstr[3];
    int nseg;
    const float* addend = nullptr;
    bool add_bias = false;

    if (mode == 1) {
        Aseg[0] = g_h1; Bseg[0] = w_hh1; bstr[0] = 1024;
        nseg = 1;
        addend = g_X1 + (size_t)t * 64 * 4096;
    } else {
        Aseg[0] = g_vatt; Bseg[0] = w_ih2;        bstr[0] = 2048;
        Aseg[1] = g_h1;   Bseg[1] = w_ih2 + 1024; bstr[1] = 2048;
        Aseg[2] = g_h2;   Bseg[2] = w_hh2;        bstr[2] = 1024;
        nseg = 3;
        add_bias = true;
    }

    const int tid = threadIdx.x;
    const int c0 = blockIdx.x * 32;
    const int ty = tid >> 3;          // 0..15 -> rows
    const int tx = tid & 7;           // 0..7  -> cols
    const int brr = tid >> 2;         // 0..31 for B loads
    const int bkk = (tid & 3) * 4;

    float acc[4][4] = {};

    for (int s = 0; s < nseg; s++) {
        const float* A = Aseg[s];
        const float* B = Bseg[s];
        const int bs = bstr[s];
        for (int kt = 0; kt < 1024; kt += 16) {
            #pragma unroll
            for (int u = 0; u < 2; u++) {
                int idx = tid + u * 128;
                int lr = idx >> 2, lk = (idx & 3) * 4;
                float4 a = *(const float4*)(A + (size_t)lr * 1024 + kt + lk);
                As[lk + 0][lr] = a.x; As[lk + 1][lr] = a.y;
                As[lk + 2][lr] = a.z; As[lk + 3][lr] = a.w;
            }
            {
                float4 bv = *(const float4*)(B + (size_t)(c0 + brr) * bs + kt + bkk);
                Bs[bkk + 0][brr] = bv.x; Bs[bkk + 1][brr] = bv.y;
                Bs[bkk + 2][brr] = bv.z; Bs[bkk + 3][brr] = bv.w;
            }
            __syncthreads();

            #pragma unroll
            for (int k = 0; k < 16; k++) {
                float4 av = *(const float4*)&As[k][ty * 4];
                float4 bw = *(const float4*)&Bs[k][tx * 4];
                float ar[4] = {av.x, av.y, av.z, av.w};
                float br[4] = {bw.x, bw.y, bw.z, bw.w};
                #pragma unroll
                for (int i = 0; i < 4; i++)
                    #pragma unroll
                    for (int j = 0; j < 4; j++)
                        acc[i][j] += ar[i] * br[j];
            }
            __syncthreads();
        }
    }

    #pragma unroll
    for (int i = 0; i < 4; i++)
        #pragma unroll
        for (int j = 0; j < 4; j++) {
            int m = ty * 4 + i;
            int c = c0 + tx * 4 + j;
            float v = acc[i][j];
            if (addend)   v += addend[(size_t)m * 4096 + c];
            if (add_bias) v += b_ih2[c] + b_hh2[c];
            g_gates[(size_t)m * 4096 + c] = v;
        }
}

// ---------------- LSTM activation (elementwise) -----------------------------
__device__ __forceinline__ float sigf(float x) { return 1.0f / (1.0f + expf(-x)); }

__global__ __launch_bounds__(256) void lstm_act(int which, float* outp) {
    int idx = blockIdx.x * blockDim.x + threadIdx.x;   // 0 .. 65535
    int m = idx >> 10;
    int d = idx & 1023;
    const float* g = g_gates + (size_t)m * 4096;
    float* h = which ? g_h2 : g_h1;
    float* c = which ? g_c2 : g_c1;

    float ig = sigf(g[d]);
    float fg = sigf(g[d + 1024]);
    float gg = tanhf(g[d + 2048]);
    float og = sigf(g[d + 3072]);
    float cn = fg * c[idx] + ig * gg;
    float hn = og * tanhf(cn);
    c[idx] = cn;
    h[idx] = hn;
    if (outp) outp[idx] = hn;
}

// ---------------- attention: alpha[n,l] = h1[n,:] . F[n,l,:] ----------------
__global__ __launch_bounds__(256) void attn_alpha(const float* __restrict__ img) {
    __shared__ float sh[1024];
    const int n = blockIdx.x;
    const int lbase = blockIdx.y * 28;
    {
        int i = threadIdx.x;
        *(float4*)&sh[i * 4] = *(const float4*)(g_h1 + (size_t)n * 1024 + i * 4);
    }
    __syncthreads();

    const int w = threadIdx.x >> 5;
    const int lane = threadIdx.x & 31;
    for (int l = lbase + w; l < lbase + 28; l += 8) {
        const float* f = img + ((size_t)n * LL + l) * 1024;
        float s = 0.f;
        #pragma unroll
        for (int i = 0; i < 8; i++) {
            int d = i * 128 + lane * 4;
            float4 fv = *(const float4*)(f + d);
            s += fv.x * sh[d] + fv.y * sh[d + 1] + fv.z * sh[d + 2] + fv.w * sh[d + 3];
        }
        #pragma unroll
        for (int off = 16; off; off >>= 1)
            s += __shfl_xor_sync(0xffffffffu, s, off);
        if (lane == 0) g_alpha[n * LL + l] = s;
    }
}

// ---------------- attention: vatt[n,d] = sum_l alpha[n,l] * F[n,l,d] --------
__global__ __launch_bounds__(256) void attn_vatt(const float* __restrict__ img) {
    __shared__ float sa[LL];
    const int n = blockIdx.x;
    const int d = blockIdx.y * 256 + threadIdx.x;
    if (threadIdx.x < LL) sa[threadIdx.x] = g_alpha[n * LL + threadIdx.x];
    __syncthreads();

    const float* f = img + (size_t)n * LL * 1024 + d;
    float s = 0.f;
    #pragma unroll 4
    for (int l = 0; l < LL; l++)
        s += sa[l] * f[(size_t)l * 1024];
    g_vatt[(size_t)n * 1024 + d] = s;
}

// ---------------- launch ----------------------------------------------------
extern "C" void kernel_launch(void* const* d_in, const int* in_sizes, int n_in,
                              void* d_out, int out_size)
{
    const int*   inputs = (const int*)  d_in[0];   // (64, 32) int32
    const float* img    = (const float*)d_in[1];   // (64, 196, 1024)
    const float* emb    = (const float*)d_in[2];   // (32000, 1024)
    const float* w_ih1  = (const float*)d_in[3];   // (4096, 1024)
    const float* w_hh1  = (const float*)d_in[4];   // (4096, 1024)
    const float* b_ih1  = (const float*)d_in[5];   // (4096)
    const float* b_hh1  = (const float*)d_in[6];   // (4096)
    const float* w_ih2  = (const float*)d_in[7];   // (4096, 2048)
    const float* w_hh2  = (const float*)d_in[8];   // (4096, 1024)
    const float* b_ih2  = (const float*)d_in[9];   // (4096)
    const float* b_hh2  = (const float*)d_in[10];  // (4096)
    float* out = (float*)d_out;                    // (64, 32, 1024)

    (void)in_sizes; (void)n_in; (void)out_size;

    zero_state<<<256, 256>>>();
    gemm_x1<<<dim3(64, 32), 256>>>(inputs, emb, w_ih1, b_ih1, b_hh1);

    for (int t = 0; t < TT; t++) {
        // cell 1: gates = X1[t] + h1 @ w_hh1^T ; activations -> h1, c1
        gemm_gates<<<128, 128>>>(1, t, w_hh1, w_ih2, w_hh2, b_ih2, b_hh2);
        lstm_act<<<256, 256>>>(0, nullptr);

        // attention (no softmax — raw dot weights, per reference)
        attn_alpha<<<dim3(64, 7), 256>>>(img);
        attn_vatt<<<dim3(64, 4), 256>>>(img);

        // cell 2: gates = [vatt|h1] @ w_ih2^T + h2 @ w_hh2^T + biases
        gemm_gates<<<128, 128>>>(2, t, w_hh1, w_ih2, w_hh2, b_ih2, b_hh2);
        // h2 of step t goes to output rows [t*64, t*64+64)
        lstm_act<<<256, 256>>>(1, out + (size_t)t * 64 * 1024);
    }
}